// round 8
// baseline (speedup 1.0000x reference)
#include <cuda_runtime.h>
#include <math.h>

#define NB 16
#define NT 50
#define NA 3
#define NG 76
#define PLANE (NG*NG)            // 5776
#define NC 85
#define CH (NA*NC)               // 255
#define NBT (NB*NT)              // 800
#define CELL_WORDS 181           // ceil(5776/32)
#define MASK_WORDS 8664          // ceil(48*5776/32)
#define TOTAL_CONF (NB*NA*PLANE) // 277248
#define THREADS 1024
#define GRID 148
#define PLANE4 (PLANE/4)         // 1444
#define TOTAL4 (48*PLANE4)       // 69312
#define BASE_CHUNK (TOTAL4/GRID)            // 468
#define EXTRA (TOTAL4 - BASE_CHUNK*GRID)    // 48

// ---------------- device scratch (only the ticket persists; self-resets) ----
__device__ float g_dense[GRID];
__device__ float g_b[8];      // sx, sy, sw, sh, sobj, nm, mcc, nz
__device__ int   g_done;

__device__ __forceinline__ float softplus_f(float v) {
    float a = fabsf(v);
    return fmaxf(v, 0.f) + __logf(1.f + __expf(-a));
}

__device__ __forceinline__ float block_reduce1024(float v, float* sh) {
    int lane = threadIdx.x & 31, wid = threadIdx.x >> 5;
    #pragma unroll
    for (int o = 16; o; o >>= 1) v += __shfl_down_sync(0xffffffffu, v, o);
    if (lane == 0) sh[wid] = v;
    __syncthreads();
    if (wid == 0) {
        v = sh[lane];   // exactly 32 warps
        #pragma unroll
        for (int o = 16; o; o >>= 1) v += __shfl_down_sync(0xffffffffu, v, o);
    }
    __syncthreads();
    return v;           // valid in thread 0
}

__global__ __launch_bounds__(THREADS, 1)
void k_yolo(const float* __restrict__ sample,
            const float* __restrict__ targets,
            const float* __restrict__ anchors,
            float* __restrict__ out)
{
    __shared__ unsigned s_mask[MASK_WORDS];   // 34.7 KB: (b*3+a)*5776+cell bits
    __shared__ unsigned s_zero[CELL_WORDS];   // ignore-cell union (all batches)
    __shared__ int      s_key[NBT];
    __shared__ float    s_acc[32][8];
    __shared__ float    s_red[32];
    __shared__ float    s_f[8];
    __shared__ int      s_flag;

    const int tid = threadIdx.x;
    const int blk = blockIdx.x;
    const bool sparse_blk = (blk == GRID - 1);

    // ---- 1. issue dense conf load immediately (no dependencies) ----
    int start = blk * BASE_CHUNK + min(blk, EXTRA);
    int cnt   = BASE_CHUNK + (blk < EXTRA ? 1 : 0);
    int plane = 0, off = 0;
    float4 v = make_float4(0.f, 0.f, 0.f, 0.f);
    if (tid < cnt) {
        int gi4 = start + tid;
        plane = gi4 / PLANE4;
        off   = gi4 - plane * PLANE4;
        v = ((const float4*)sample)[(size_t)(85 * plane + 4) * PLANE4 + off];
    }

    // ---- 2. issue target loads (also independent) ----
    float tl=0.f, tcx=0.f, tcy=0.f, tcw=0.f, tch=0.f;
    float r1=0.f, r2=0.f, r3=0.f, r4=0.f;
    int b = 0;
    if (tid < NBT) {
        b = tid / NT;
        const float* tg = targets + (size_t)tid * 5;
        const float* t0 = targets + (size_t)(b * NT) * 5;
        tl = tg[0]; tcx = tg[1]; tcy = tg[2]; tcw = tg[3]; tch = tg[4];
        r1 = t0[1]; r2 = t0[2]; r3 = t0[3]; r4 = t0[4];
    }
    const float stride = 608.0f / (float)NG;   // 8
    float awS[NA], ahS[NA];
    #pragma unroll
    for (int a = 0; a < NA; a++) {
        awS[a] = anchors[2*a]   / stride;
        ahS[a] = anchors[2*a+1] / stride;
    }

    // ---- 3. zero shared bitmaps while loads are in flight ----
    #pragma unroll
    for (int i = 0; i < 9; i++) {
        int w = tid + i * THREADS;
        if (w < MASK_WORDS) s_mask[w] = 0u;
    }
    if (tid < CELL_WORDS) s_zero[tid] = 0u;

    // ---- 4. per-target math ----
    float gx=0.f, gy=0.f, gw=0.f, gh=0.f;
    int bn = 0, cell = 0;
    bool ign = false;
    if (tid < NBT) {
        float s5 = tl + tcx + tcy + tcw + tch;
        bool mm = s5 > 0.f;
        gx = (mm ? tcx : r1) * NG;
        gy = (mm ? tcy : r2) * NG;
        gw = (mm ? tcw : r3) * NG;
        gh = (mm ? tch : r4) * NG;
        int gi = (int)gx, gj = (int)gy;
        float best = -1e30f;
        #pragma unroll
        for (int a = 0; a < NA; a++) {
            float iw = fminf(gw, awS[a]) + 1.f;
            float ih = fminf(gh, ahS[a]) + 1.f;
            float inter = fmaxf(iw, 0.f) * fmaxf(ih, 0.f);
            float denom = (gw + 1.f) * (gh + 1.f)
                        + (awS[a] + 1.f) * (ahS[a] + 1.f) - inter + 1e-12f;
            float iou = __fdividef(inter, denom);
            ign |= (iou > 0.5f);
            if (iou > best) { best = iou; bn = a; }   // first-max wins ties
        }
        cell = gj * NG + gi;
    }
    __syncthreads();   // zeroing complete

    // ---- 5. build bitmaps + keys ----
    if (tid < NBT) {
        if (ign) atomicOr(&s_zero[cell >> 5], 1u << (cell & 31));
        int bp = (b * NA + bn) * PLANE + cell;
        atomicOr(&s_mask[bp >> 5], 1u << (bp & 31));
        s_key[tid] = bn * PLANE + cell;   // within-batch key
    }

    // ---- 6. sparse block: issue pred gather early (address already known) ----
    float p0=0.f, p1=0.f, p2=0.f, p3=0.f, p4=0.f;
    if (sparse_blk && tid < NBT) {
        size_t poff = ((size_t)(b * CH + bn * NC)) * PLANE + (size_t)cell;
        p0 = sample[poff];
        p1 = sample[poff + 1 * PLANE];
        p2 = sample[poff + 2 * PLANE];
        p3 = sample[poff + 3 * PLANE];
        p4 = sample[poff + 4 * PLANE];
    }
    __syncthreads();   // bitmaps complete

    // ---- 7. dense masked BCE (branchless, masks folded into log-product) ----
    float s = 0.f;
    if (tid < cnt) {
        int cb = off * 4;                      // cell base (4 consecutive cells)
        unsigned zw = s_zero[cb >> 5] >> (cb & 31);
        int bp = plane * PLANE + cb;           // bp is a multiple of 4 -> no straddle
        unsigned mw = s_mask[bp >> 5] >> (bp & 31);
        unsigned ex = zw | mw;                 // exclusion bits 0..3
        float m0 = (float)(1u - (ex & 1u));
        float m1 = (float)(1u - ((ex >> 1) & 1u));
        float m2 = (float)(1u - ((ex >> 2) & 1u));
        float m3 = (float)(1u - ((ex >> 3) & 1u));
        float srelu = m0 * fmaxf(v.x, 0.f) + m1 * fmaxf(v.y, 0.f)
                    + m2 * fmaxf(v.z, 0.f) + m3 * fmaxf(v.w, 0.f);
        float p = (1.f + m0 * __expf(-fabsf(v.x)))
                * (1.f + m1 * __expf(-fabsf(v.y)))
                * (1.f + m2 * __expf(-fabsf(v.z)))
                * (1.f + m3 * __expf(-fabsf(v.w)));
        s = srelu + __logf(p);                 // 4 exp + 1 log per float4
    }
    float rs = block_reduce1024(s, s_red);
    if (tid == 0) { g_dense[blk] = rs; __threadfence(); }

    // ---- 8. sparse block: winner losses + counts ----
    if (sparse_blk) {
        float acc[8];
        #pragma unroll
        for (int c = 0; c < 8; c++) acc[c] = 0.f;

        if (tid < NBT) {
            int mykey = s_key[tid];
            int base = b * NT, ti = tid - base;
            bool winner = true;                 // last-wins scan within batch
            #pragma unroll
            for (int t2 = 0; t2 < NT; t2++)
                winner &= !((t2 > ti) & (s_key[base + t2] == mykey));
            if (winner) {
                int gi = (int)gx, gj = (int)gy;
                float x  = __fdividef(1.f, 1.f + __expf(-p0));
                float y  = __fdividef(1.f, 1.f + __expf(-p1));
                float pc = __fdividef(1.f, 1.f + __expf(-p4));
                float tx = gx - (float)gi;
                float ty = gy - (float)gj;
                float tw = __logf(__fdividef(gw, awS[bn]) + 1e-16f);
                float th = __logf(__fdividef(gh, ahS[bn]) + 1e-16f);
                float dx = x - tx, dy = y - ty, dw = p2 - tw, dh = p3 - th;
                acc[0] = dx*dx; acc[1] = dy*dy; acc[2] = dw*dw; acc[3] = dh*dh;
                acc[4] = -__logf(pc + 1e-12f);
                acc[5] = 1.f;                                   // nm
                if (!((s_zero[cell >> 5] >> (cell & 31)) & 1u))
                    acc[6] = 1.f;                               // mcc
            }
        }
        if (tid < CELL_WORDS) acc[7] = (float)__popc(s_zero[tid]);  // nz

        int lane = tid & 31, wid = tid >> 5;
        #pragma unroll
        for (int c = 0; c < 8; c++)
            #pragma unroll
            for (int o = 16; o; o >>= 1)
                acc[c] += __shfl_down_sync(0xffffffffu, acc[c], o);
        if (lane == 0)
            #pragma unroll
            for (int c = 0; c < 8; c++) s_acc[wid][c] = acc[c];
        __syncthreads();
        if (tid < 8) {
            float sum = 0.f;
            #pragma unroll
            for (int w = 0; w < 32; w++) sum += s_acc[w][tid];
            g_b[tid] = sum;
            __threadfence();
        }
        __syncthreads();
    }

    // ---- 9. single global ticket; last block combines ----
    if (tid == 0)
        s_flag = (atomicAdd(&g_done, 1) == GRID - 1) ? 1 : 0;
    __syncthreads();
    if (s_flag) {
        __threadfence();   // acquire all blocks' writes
        float dv = (tid < GRID) ? g_dense[tid] : 0.f;
        if (tid >= 32 && tid < 40) s_f[tid - 32] = g_b[tid - 32];
        float dsum = block_reduce1024(dv, s_red);   // ends with syncthreads
        if (tid == 0) {
            float nm   = fmaxf(s_f[5], 1.f);
            float lx   = 2.0f * s_f[0] / nm;
            float ly   = 2.0f * s_f[1] / nm;
            float lw   = 1.6f * s_f[2] / nm;
            float lh   = 1.6f * s_f[3] / nm;
            float lobj = 1.0f * s_f[4] / nm;
            float ncnt = (float)TOTAL_CONF - 48.f * s_f[7] - s_f[6];
            float lnoobj = 0.5f * dsum / fmaxf(ncnt, 1.f);
            out[0] = lx + ly + lw + lh + lnoobj + lobj;
            out[1] = lx; out[2] = ly; out[3] = lw; out[4] = lh;
            out[5] = lobj; out[6] = lnoobj;
            atomicExch(&g_done, 0);   // graph-replay safe reset
        }
    }
}

extern "C" void kernel_launch(void* const* d_in, const int* in_sizes, int n_in,
                              void* d_out, int out_size)
{
    const float* sample  = (const float*)d_in[0];
    const float* targets = (const float*)d_in[1];
    const float* anchors = (const float*)d_in[2];
    float* out = (float*)d_out;

    k_yolo<<<GRID, THREADS>>>(sample, targets, anchors, out);
}

// round 9
// speedup vs baseline: 1.1946x; 1.1946x over previous
#include <cuda_runtime.h>
#include <math.h>

#define NB 16
#define NT 50
#define NA 3
#define NG 76
#define PLANE 5776
#define NC 85
#define CH 255
#define NBT 800
#define CELL_WORDS 181
#define TOTAL_CONF 277248
#define THREADS 512
#define GRID 148
#define PLANE4 1444
#define TOTAL4 69312
#define BASE_CHUNK 468          // 69312/148
#define EXTRA 48                // first 48 blocks take one more

// ---------------- device scratch (combiner resets everything) ----------------
__device__ float g_acc[8];   // sx, sy, sw, sh, sobj, nm, mcc, nz
__device__ float g_dsum;     // dense softplus sum minus all corrections
__device__ int   g_done;

__device__ __forceinline__ float softplus_f(float v) {
    float a = fabsf(v);
    return fmaxf(v, 0.f) + __logf(1.f + __expf(-a));
}

__device__ __forceinline__ float block_reduce512(float v, float* sh) {
    int lane = threadIdx.x & 31, wid = threadIdx.x >> 5;
    #pragma unroll
    for (int o = 16; o; o >>= 1) v += __shfl_down_sync(0xffffffffu, v, o);
    if (lane == 0) sh[wid] = v;
    __syncthreads();
    if (wid == 0) {
        v = (lane < 16) ? sh[lane] : 0.f;
        #pragma unroll
        for (int o = 8; o; o >>= 1) v += __shfl_down_sync(0xffffffffu, v, o);
    }
    __syncthreads();
    return v;   // valid in thread 0
}

__global__ __launch_bounds__(THREADS)
void k_yolo(const float* __restrict__ sample,
            const float* __restrict__ targets,
            const float* __restrict__ anchors,
            float* __restrict__ out)
{
    __shared__ unsigned s_zero[CELL_WORDS];
    __shared__ int      s_zlist[NBT];
    __shared__ int      s_nz;
    __shared__ int      s_key[NT];
    __shared__ float    s_g4[NT][4];
    __shared__ float    s_accw[16][8];
    __shared__ float    s_red[16];
    __shared__ float    s_f[9];
    __shared__ int      s_flag;

    const int tid = threadIdx.x;
    const int blk = blockIdx.x;
    const bool builder = (blk < NB);

    // ---- dense conf load: issued first, no dependencies ----
    int start = blk * BASE_CHUNK + min(blk, EXTRA);
    int cnt   = BASE_CHUNK + (blk < EXTRA ? 1 : 0);
    float4 v = make_float4(0.f, 0.f, 0.f, 0.f);
    if (tid < cnt) {
        int gi4 = start + tid;
        int plane = gi4 / PLANE4;
        int off   = gi4 - plane * PLANE4;
        v = ((const float4*)sample)[(size_t)(85 * plane + 4) * PLANE4 + off];
    }

    float acc[8];
    #pragma unroll
    for (int c = 0; c < 8; c++) acc[c] = 0.f;
    float csub = 0.f;   // corrections, subtracted from this block's dense sum

    if (builder) {
        const int b = blk;
        float awS[NA], ahS[NA];
        #pragma unroll
        for (int a = 0; a < NA; a++) {
            awS[a] = anchors[2*a]   * 0.125f;   // /8 (stride = 608/76)
            ahS[a] = anchors[2*a+1] * 0.125f;
        }
        if (tid < CELL_WORDS) s_zero[tid] = 0u;
        if (tid == 0) s_nz = 0;

        // ---- all 800 targets in two register chunks (loads batched) ----
        int   cellC[2], bnC[2];
        bool  ignC[2], actC[2];
        float gxC[2], gyC[2], gwC[2], ghC[2];
        #pragma unroll
        for (int c = 0; c < 2; c++) {
            int t = tid + c * THREADS;
            actC[c] = (t < NBT);
            ignC[c] = false; cellC[c] = 0; bnC[c] = 0;
            gxC[c] = gyC[c] = gwC[c] = ghC[c] = 0.f;
            if (actC[c]) {
                int bt = t / NT;
                const float* tg = targets + (size_t)t * 5;
                const float* t0 = targets + (size_t)(bt * NT) * 5;
                float s5 = tg[0] + tg[1] + tg[2] + tg[3] + tg[4];
                bool mm = s5 > 0.f;
                float gx = (mm ? tg[1] : t0[1]) * NG;
                float gy = (mm ? tg[2] : t0[2]) * NG;
                float gw = (mm ? tg[3] : t0[3]) * NG;
                float gh = (mm ? tg[4] : t0[4]) * NG;
                float best = -1e30f; int bn = 0; bool ign = false;
                #pragma unroll
                for (int a = 0; a < NA; a++) {
                    float iw = fminf(gw, awS[a]) + 1.f;
                    float ih = fminf(gh, ahS[a]) + 1.f;
                    float inter = fmaxf(iw, 0.f) * fmaxf(ih, 0.f);
                    float denom = (gw + 1.f) * (gh + 1.f)
                                + (awS[a] + 1.f) * (ahS[a] + 1.f) - inter + 1e-12f;
                    float iou = __fdividef(inter, denom);
                    ign |= (iou > 0.5f);
                    if (iou > best) { best = iou; bn = a; }   // first-max ties
                }
                gxC[c] = gx; gyC[c] = gy; gwC[c] = gw; ghC[c] = gh;
                bnC[c] = bn; ignC[c] = ign;
                cellC[c] = ((int)gy) * NG + (int)gx;
            }
        }
        __syncthreads();   // s_zero zeroing complete

        #pragma unroll
        for (int c = 0; c < 2; c++) {
            int t = tid + c * THREADS;
            if (actC[c]) {
                if (ignC[c])
                    atomicOr(&s_zero[cellC[c] >> 5], 1u << (cellC[c] & 31));
                int lo = b * NT;
                if (t >= lo && t < lo + NT) {      // own-batch target
                    int ti = t - lo;
                    s_key[ti] = bnC[c] * PLANE + cellC[c];
                    s_g4[ti][0] = gxC[c]; s_g4[ti][1] = gyC[c];
                    s_g4[ti][2] = gwC[c]; s_g4[ti][3] = ghC[c];
                }
            }
        }
        __syncthreads();

        // compact ignore-cell list
        if (tid < CELL_WORDS) {
            unsigned w = s_zero[tid];
            if (w) {
                int pos = atomicAdd(&s_nz, __popc(w));
                while (w) {
                    int bit = __ffs(w) - 1; w &= w - 1;
                    s_zlist[pos++] = tid * 32 + bit;
                }
            }
        }
        __syncthreads();
        int nz = s_nz;

        // ---- winners of own batch: sparse losses + winner corrections ----
        if (tid < NT) {
            int mykey = s_key[tid];
            bool winner = true;                   // last-wins scan
            #pragma unroll
            for (int t2 = 0; t2 < NT; t2++)
                winner &= !((t2 > tid) & (s_key[t2] == mykey));
            if (winner) {
                int cell = mykey % PLANE;
                int bn   = mykey / PLANE;
                float gx = s_g4[tid][0], gy = s_g4[tid][1];
                float gw = s_g4[tid][2], gh = s_g4[tid][3];
                int gi = (int)gx, gj = (int)gy;
                size_t poff = ((size_t)(b * CH + bn * NC)) * PLANE + (size_t)cell;
                float p0 = sample[poff];
                float p1 = sample[poff + 1 * PLANE];
                float p2 = sample[poff + 2 * PLANE];
                float p3 = sample[poff + 3 * PLANE];
                float p4 = sample[poff + 4 * PLANE];

                float x  = __fdividef(1.f, 1.f + __expf(-p0));
                float y  = __fdividef(1.f, 1.f + __expf(-p1));
                float pc = __fdividef(1.f, 1.f + __expf(-p4));
                float tx = gx - (float)gi;
                float ty = gy - (float)gj;
                float tw = __logf(__fdividef(gw, awS[bn]) + 1e-16f);
                float th = __logf(__fdividef(gh, ahS[bn]) + 1e-16f);
                float dx = x - tx, dy = y - ty, dw = p2 - tw, dh = p3 - th;
                acc[0] = dx*dx; acc[1] = dy*dy; acc[2] = dw*dw; acc[3] = dh*dh;
                acc[4] = -__logf(pc + 1e-12f);
                acc[5] = 1.f;                                  // nm
                if (!((s_zero[cell >> 5] >> (cell & 31)) & 1u)) {
                    acc[6] = 1.f;                              // mcc
                    csub += softplus_f(p4);                    // winner correction
                }
            }
        }

        // ---- ignore-cell corrections: this builder covers planes 3b..3b+2 ----
        for (int i = tid; i < 3 * nz; i += THREADS) {
            int cell = s_zlist[i / 3];
            int p = 3 * b + i % 3;
            csub += softplus_f(sample[(size_t)(85 * p + 4) * PLANE + (size_t)cell]);
        }
        if (b == 0 && tid == 0) acc[7] = (float)nz;
    }

    // ---- dense masked-later softplus (4 exp + 1 log per float4) ----
    float s = 0.f;
    if (tid < cnt) {
        float srelu = fmaxf(v.x, 0.f) + fmaxf(v.y, 0.f)
                    + fmaxf(v.z, 0.f) + fmaxf(v.w, 0.f);
        float p = (1.f + __expf(-fabsf(v.x)))
                * (1.f + __expf(-fabsf(v.y)))
                * (1.f + __expf(-fabsf(v.z)))
                * (1.f + __expf(-fabsf(v.w)));
        s = srelu + __logf(p);
    }
    s -= csub;

    float rs = block_reduce512(s, s_red);
    if (tid == 0) atomicAdd(&g_dsum, rs);

    if (builder) {   // 8-way reduce sparse terms, 8 parallel atomics
        int lane = tid & 31, wid = tid >> 5;
        #pragma unroll
        for (int c = 0; c < 8; c++)
            #pragma unroll
            for (int o = 16; o; o >>= 1)
                acc[c] += __shfl_down_sync(0xffffffffu, acc[c], o);
        if (lane == 0)
            #pragma unroll
            for (int c = 0; c < 8; c++) s_accw[wid][c] = acc[c];
        __syncthreads();
        if (tid < 8) {
            float sum = 0.f;
            #pragma unroll
            for (int w = 0; w < 16; w++) sum += s_accw[w][tid];
            atomicAdd(&g_acc[tid], sum);
        }
    }

    __threadfence();
    __syncthreads();

    // ---- single ticket; last block combines in one scalar round ----
    if (tid == 0)
        s_flag = (atomicAdd(&g_done, 1) == GRID - 1) ? 1 : 0;
    __syncthreads();
    if (s_flag) {
        __threadfence();
        if (tid < 8) s_f[tid] = g_acc[tid];
        if (tid == 8) s_f[8] = g_dsum;
        __syncthreads();
        if (tid < 8) g_acc[tid] = 0.f;        // reset for next replay
        if (tid == 8) g_dsum = 0.f;
        if (tid == 0) {
            float nm   = fmaxf(s_f[5], 1.f);
            float lx   = 2.0f * s_f[0] / nm;
            float ly   = 2.0f * s_f[1] / nm;
            float lw   = 1.6f * s_f[2] / nm;
            float lh   = 1.6f * s_f[3] / nm;
            float lobj = 1.0f * s_f[4] / nm;
            float ncnt = (float)TOTAL_CONF - 48.f * s_f[7] - s_f[6];
            float lnoobj = 0.5f * s_f[8] / fmaxf(ncnt, 1.f);
            out[0] = lx + ly + lw + lh + lnoobj + lobj;
            out[1] = lx; out[2] = ly; out[3] = lw; out[4] = lh;
            out[5] = lobj; out[6] = lnoobj;
            atomicExch(&g_done, 0);
        }
    }
}

extern "C" void kernel_launch(void* const* d_in, const int* in_sizes, int n_in,
                              void* d_out, int out_size)
{
    const float* sample  = (const float*)d_in[0];
    const float* targets = (const float*)d_in[1];
    const float* anchors = (const float*)d_in[2];
    float* out = (float*)d_out;

    k_yolo<<<GRID, THREADS>>>(sample, targets, anchors, out);
}